// round 1
// baseline (speedup 1.0000x reference)
#include <cuda_runtime.h>
#include <math.h>

#define B1n 4
#define B2n 1024
#define Rn  64
#define Tn  8192
#define Ln  256

__global__ void __launch_bounds__(Ln, 4)
tof_predictor_kernel(const float* __restrict__ rec,        // (B1,R,T)
                     const float* __restrict__ samp,       // (B1,B2,3)
                     const float* __restrict__ emit,       // (3,)
                     const float* __restrict__ recv,       // (R,3)
                     float* __restrict__ out)              // (B1,B2)
{
    const int b2 = blockIdx.x;
    const int b1 = blockIdx.y;
    const int l  = threadIdx.x;

    __shared__ float s_start[Rn];
    __shared__ float s_red[16];   // 8 warps x 2 values

    // ---- precompute fractional start index per receiver (threads 0..63) ----
    const float fs_c = 96000.0f / 343.0f;
    if (l < Rn) {
        const float* sp = samp + ((size_t)b1 * B2n + b2) * 3;
        float sx = sp[0], sy = sp[1], sz = sp[2];
        float ex = sx - emit[0], ey = sy - emit[1], ez = sz - emit[2];
        float d_e = sqrtf(ex * ex + ey * ey + ez * ez);
        const float* rp = recv + l * 3;
        float rx = sx - rp[0], ry = sy - rp[1], rz = sz - rp[2];
        float d_r = sqrtf(rx * rx + ry * ry + rz * rz);
        s_start[l] = (d_e + d_r) * fs_c;
    }
    __syncthreads();

    // Hann half-window: 0.5 - 0.5*cos(pi * l / (L-1))
    const float w = 0.5f - 0.5f * cosf(3.14159265358979323846f * (float)l * (1.0f / 255.0f));
    const float fl = (float)l;

    const float* recb = rec + (size_t)b1 * Rn * Tn;

    float s1 = 0.0f;  // sum over r of xw
    float s2 = 0.0f;  // sum over r of xw^2

#pragma unroll 8
    for (int r = 0; r < Rn; ++r) {
        float idx = s_start[r] + fl;
        int i0 = (int)floorf(idx);
        i0 = min(max(i0, 0), Tn - 2);
        float frac = idx - (float)i0;
        const float* p = recb + r * Tn + i0;
        float v0 = __ldg(p);
        float v1 = __ldg(p + 1);
        float xw = fmaf(frac, v1 - v0, v0) * w;
        s1 += xw;
        s2 = fmaf(xw, xw, s2);
    }

    // per-thread (per-l) contributions:
    //   num_l = s2               (summed over l, then /(R*L))
    //   den_l = (s2 - s1^2/R)/(R-1)   (summed over l, then /L, + 0.001)
    float num_p = s2;
    float den_p = (s2 - s1 * s1 * (1.0f / (float)Rn)) * (1.0f / (float)(Rn - 1));

    // ---- block reduction of (num_p, den_p) over 256 threads ----
    const unsigned FULL = 0xFFFFFFFFu;
#pragma unroll
    for (int off = 16; off > 0; off >>= 1) {
        num_p += __shfl_down_sync(FULL, num_p, off);
        den_p += __shfl_down_sync(FULL, den_p, off);
    }
    const int warp = l >> 5;
    const int lane = l & 31;
    if (lane == 0) {
        s_red[warp * 2 + 0] = num_p;
        s_red[warp * 2 + 1] = den_p;
    }
    __syncthreads();
    if (warp == 0) {
        float n = (lane < 8) ? s_red[lane * 2 + 0] : 0.0f;
        float d = (lane < 8) ? s_red[lane * 2 + 1] : 0.0f;
#pragma unroll
        for (int off = 4; off > 0; off >>= 1) {
            n += __shfl_down_sync(FULL, n, off);
            d += __shfl_down_sync(FULL, d, off);
        }
        if (lane == 0) {
            float num = n * (1.0f / ((float)Rn * (float)Ln));
            float den = d * (1.0f / (float)Ln) + 0.001f;
            out[(size_t)b1 * B2n + b2] = num / den;
        }
    }
}

extern "C" void kernel_launch(void* const* d_in, const int* in_sizes, int n_in,
                              void* d_out, int out_size)
{
    const float* recordings         = (const float*)d_in[0];
    const float* sample_locations   = (const float*)d_in[1];
    const float* emitter_location   = (const float*)d_in[2];
    const float* receiver_locations = (const float*)d_in[3];
    float* out = (float*)d_out;

    dim3 grid(B2n, B1n);
    dim3 block(Ln);
    tof_predictor_kernel<<<grid, block>>>(recordings, sample_locations,
                                          emitter_location, receiver_locations, out);
}

// round 2
// speedup vs baseline: 1.0339x; 1.0339x over previous
#include <cuda_runtime.h>
#include <math.h>

#define B1n 4
#define B2n 1024
#define Rn  64
#define Tn  8192
#define Ln  256

__global__ void __launch_bounds__(Ln)
tof_predictor_kernel(const float* __restrict__ rec,        // (B1,R,T)
                     const float* __restrict__ samp,       // (B1,B2,3)
                     const float* __restrict__ emit,       // (3,)
                     const float* __restrict__ recv,       // (R,3)
                     float* __restrict__ out)              // (B1,B2)
{
    const int b2 = blockIdx.x;
    const int b1 = blockIdx.y;
    const int l  = threadIdx.x;

    // s_pr[r] = { frac, as_float(r*Tn + i0_base) }  -> single LDS.64 per iter
    __shared__ float2 s_pr[Rn];
    __shared__ float  s_red[16];   // 8 warps x 2 values

    // ---- precompute per-receiver base index + frac (threads 0..63) ----
    const float fs_c = 96000.0f / 343.0f;
    if (l < Rn) {
        const float* sp = samp + ((size_t)b1 * B2n + b2) * 3;
        float sx = sp[0], sy = sp[1], sz = sp[2];
        float ex = sx - emit[0], ey = sy - emit[1], ez = sz - emit[2];
        float d_e = sqrtf(ex * ex + ey * ey + ez * ez);
        const float* rp = recv + l * 3;
        float rx = sx - rp[0], ry = sy - rp[1], rz = sz - rp[2];
        float d_r = sqrtf(rx * rx + ry * ry + rz * rz);
        float start = (d_e + d_r) * fs_c;
        float i0f = floorf(start);
        int   i0  = (int)i0f;
        // safety clamp (mathematically never fires for this geometry;
        // exact-equivalent when in range)
        i0 = min(max(i0, 0), Tn - 2 - (Ln - 1));
        float frac = start - (float)i0;
        s_pr[l] = make_float2(frac, __int_as_float(l * Tn + i0));
    }
    __syncthreads();

    // Hann half-window: 0.5 - 0.5*cos(pi * l / (L-1)); hoisted out of r-loop.
    const float w = 0.5f - 0.5f * cosf(3.14159265358979323846f * (float)l * (1.0f / 255.0f));

    const float* base_l = rec + (size_t)b1 * Rn * Tn + l;
    const unsigned FULL = 0xFFFFFFFFu;
    const bool last_lane = ((l & 31) == 31);

    float s1 = 0.0f;  // sum over r of lerp
    float s2 = 0.0f;  // sum over r of lerp^2

#pragma unroll 16
    for (int r = 0; r < Rn; ++r) {
        float2 pr = s_pr[r];
        const float* p = base_l + __float_as_int(pr.y);
        float v0 = __ldg(p);
        float v1 = __shfl_down_sync(FULL, v0, 1);
        if (last_lane) v1 = __ldg(p + 1);
        float lerp = fmaf(pr.x, v1 - v0, v0);
        s1 += lerp;
        s2 = fmaf(lerp, lerp, s2);
    }

    // apply window factors after the reduction over r:
    //   xw       = lerp * w
    //   sum xw   = w   * s1
    //   sum xw^2 = w^2 * s2
    float sw1 = w * s1;
    float sw2 = (w * w) * s2;

    // per-thread (per-l) contributions:
    //   num_l = sw2                         (summed over l, /(R*L))
    //   den_l = (sw2 - sw1^2/R)/(R-1)      (summed over l, /L, +0.001)
    float num_p = sw2;
    float den_p = (sw2 - sw1 * sw1 * (1.0f / (float)Rn)) * (1.0f / (float)(Rn - 1));

    // ---- block reduction of (num_p, den_p) over 256 threads ----
#pragma unroll
    for (int off = 16; off > 0; off >>= 1) {
        num_p += __shfl_down_sync(FULL, num_p, off);
        den_p += __shfl_down_sync(FULL, den_p, off);
    }
    const int warp = l >> 5;
    const int lane = l & 31;
    if (lane == 0) {
        s_red[warp * 2 + 0] = num_p;
        s_red[warp * 2 + 1] = den_p;
    }
    __syncthreads();
    if (warp == 0) {
        float n = (lane < 8) ? s_red[lane * 2 + 0] : 0.0f;
        float d = (lane < 8) ? s_red[lane * 2 + 1] : 0.0f;
#pragma unroll
        for (int off = 4; off > 0; off >>= 1) {
            n += __shfl_down_sync(FULL, n, off);
            d += __shfl_down_sync(FULL, d, off);
        }
        if (lane == 0) {
            float num = n * (1.0f / ((float)Rn * (float)Ln));
            float den = d * (1.0f / (float)Ln) + 0.001f;
            out[(size_t)b1 * B2n + b2] = num / den;
        }
    }
}

extern "C" void kernel_launch(void* const* d_in, const int* in_sizes, int n_in,
                              void* d_out, int out_size)
{
    const float* recordings         = (const float*)d_in[0];
    const float* sample_locations   = (const float*)d_in[1];
    const float* emitter_location   = (const float*)d_in[2];
    const float* receiver_locations = (const float*)d_in[3];
    float* out = (float*)d_out;

    dim3 grid(B2n, B1n);
    dim3 block(Ln);
    tof_predictor_kernel<<<grid, block>>>(recordings, sample_locations,
                                          emitter_location, receiver_locations, out);
}

// round 3
// speedup vs baseline: 1.2949x; 1.2524x over previous
#include <cuda_runtime.h>
#include <math.h>

#define B1n 4
#define B2n 1024
#define Rn  64
#define Tn  8192
#define Ln  256

// Each thread owns 4 consecutive l values. 256 threads = 64 l-threads x 4 r-groups.
// Window base i0a is 4-aligned -> two aligned LDG.128 cover the 5 needed samples.

__global__ void __launch_bounds__(Ln)
tof_predictor_kernel(const float* __restrict__ rec,        // (B1,R,T)
                     const float* __restrict__ samp,       // (B1,B2,3)
                     const float* __restrict__ emit,       // (3,)
                     const float* __restrict__ recv,       // (R,3)
                     float* __restrict__ out)              // (B1,B2)
{
    const int b2  = blockIdx.x;
    const int b1  = blockIdx.y;
    const int tid = threadIdx.x;

    __shared__ float2 s_pr[Rn];          // {frac, as_float((r*Tn+i0a)<<2 | d)}
    __shared__ float  s_w[Ln];           // Hann window
    __shared__ float  s_s1[4 * Ln];      // per-group partial sums of lerp
    __shared__ float  s_s2[4 * Ln];      // per-group partial sums of lerp^2
    __shared__ float  s_red[16];

    // ---- precompute per-receiver base + frac (threads 0..63) ----
    const float fs_c = 96000.0f / 343.0f;
    if (tid < Rn) {
        const float* sp = samp + ((size_t)b1 * B2n + b2) * 3;
        float sx = sp[0], sy = sp[1], sz = sp[2];
        float ex = sx - emit[0], ey = sy - emit[1], ez = sz - emit[2];
        float d_e = sqrtf(ex * ex + ey * ey + ez * ez);
        const float* rp = recv + tid * 3;
        float rx = sx - rp[0], ry = sy - rp[1], rz = sz - rp[2];
        float d_r = sqrtf(rx * rx + ry * ry + rz * rz);
        float start = (d_e + d_r) * fs_c;
        int i0 = (int)floorf(start);
        i0 = min(max(i0, 0), Tn - 8 - Ln);          // never fires for this geometry
        float frac = start - (float)i0;             // in [0,1)
        int i0a = i0 & ~3;
        int d   = i0 & 3;
        int packed = ((tid * Tn + i0a) << 2) | d;
        s_pr[tid] = make_float2(frac, __int_as_float(packed));
    }
    // Hann half-window (all 256 threads, one each)
    s_w[tid] = 0.5f - 0.5f * cosf(3.14159265358979323846f * (float)tid * (1.0f / 255.0f));
    __syncthreads();

    const int g = tid >> 6;        // r-group 0..3  -> handles r = g*16 .. g*16+15
    const int t = tid & 63;        // l-thread      -> l = 4t .. 4t+3

    const float* recb = rec + (size_t)b1 * Rn * Tn + 4 * t;

    float a0 = 0.f, a1 = 0.f, a2 = 0.f, a3 = 0.f;   // sum lerp per l
    float q0 = 0.f, q1 = 0.f, q2 = 0.f, q3 = 0.f;   // sum lerp^2 per l

    const int r_lo = g * 16;
#pragma unroll 4
    for (int r = r_lo; r < r_lo + 16; ++r) {
        float2 pb = s_pr[r];
        float  f  = pb.x;
        int    od = __float_as_int(pb.y);
        int    d  = od & 3;
        const float4* p = (const float4*)(recb + (od >> 2));
        float4 A = __ldg(p);
        float4 B = __ldg(p + 1);

        float w0, w1, w2, w3, w4;
        if (d == 0)      { w0=A.x; w1=A.y; w2=A.z; w3=A.w; w4=B.x; }
        else if (d == 1) { w0=A.y; w1=A.z; w2=A.w; w3=B.x; w4=B.y; }
        else if (d == 2) { w0=A.z; w1=A.w; w2=B.x; w3=B.y; w4=B.z; }
        else             { w0=A.w; w1=B.x; w2=B.y; w3=B.z; w4=B.w; }

        float e0 = fmaf(f, w1 - w0, w0);
        float e1 = fmaf(f, w2 - w1, w1);
        float e2 = fmaf(f, w3 - w2, w2);
        float e3 = fmaf(f, w4 - w3, w3);
        a0 += e0; q0 = fmaf(e0, e0, q0);
        a1 += e1; q1 = fmaf(e1, e1, q1);
        a2 += e2; q2 = fmaf(e2, e2, q2);
        a3 += e3; q3 = fmaf(e3, e3, q3);
    }

    // store per-group partials (16B-aligned vector stores)
    {
        float4* p1 = (float4*)&s_s1[g * Ln + 4 * t];
        float4* p2 = (float4*)&s_s2[g * Ln + 4 * t];
        *p1 = make_float4(a0, a1, a2, a3);
        *p2 = make_float4(q0, q1, q2, q3);
    }
    __syncthreads();

    // combine across the 4 r-groups: thread tid owns l = tid
    float S1 = s_s1[tid] + s_s1[Ln + tid] + s_s1[2 * Ln + tid] + s_s1[3 * Ln + tid];
    float S2 = s_s2[tid] + s_s2[Ln + tid] + s_s2[2 * Ln + tid] + s_s2[3 * Ln + tid];

    float wl  = s_w[tid];
    float w2l = wl * wl;
    float sw1 = wl * S1;               // sum_r xw
    float sw2 = w2l * S2;              // sum_r xw^2

    float num_p = sw2;
    float den_p = (sw2 - sw1 * sw1 * (1.0f / (float)Rn)) * (1.0f / (float)(Rn - 1));

    // ---- block reduction of (num_p, den_p) over 256 threads ----
    const unsigned FULL = 0xFFFFFFFFu;
#pragma unroll
    for (int off = 16; off > 0; off >>= 1) {
        num_p += __shfl_down_sync(FULL, num_p, off);
        den_p += __shfl_down_sync(FULL, den_p, off);
    }
    const int warp = tid >> 5;
    const int lane = tid & 31;
    if (lane == 0) {
        s_red[warp * 2 + 0] = num_p;
        s_red[warp * 2 + 1] = den_p;
    }
    __syncthreads();
    if (warp == 0) {
        float n = (lane < 8) ? s_red[lane * 2 + 0] : 0.0f;
        float dd = (lane < 8) ? s_red[lane * 2 + 1] : 0.0f;
#pragma unroll
        for (int off = 4; off > 0; off >>= 1) {
            n  += __shfl_down_sync(FULL, n, off);
            dd += __shfl_down_sync(FULL, dd, off);
        }
        if (lane == 0) {
            float num = n * (1.0f / ((float)Rn * (float)Ln));
            float den = dd * (1.0f / (float)Ln) + 0.001f;
            out[(size_t)b1 * B2n + b2] = num / den;
        }
    }
}

extern "C" void kernel_launch(void* const* d_in, const int* in_sizes, int n_in,
                              void* d_out, int out_size)
{
    const float* recordings         = (const float*)d_in[0];
    const float* sample_locations   = (const float*)d_in[1];
    const float* emitter_location   = (const float*)d_in[2];
    const float* receiver_locations = (const float*)d_in[3];
    float* out = (float*)d_out;

    dim3 grid(B2n, B1n);
    dim3 block(Ln);
    tof_predictor_kernel<<<grid, block>>>(recordings, sample_locations,
                                          emitter_location, receiver_locations, out);
}